// round 14
// baseline (speedup 1.0000x reference)
#include <cuda_runtime.h>
#include <cuda_fp16.h>
#include <cstdint>

// ---------------------------------------------------------------------------
// Problem constants
// ---------------------------------------------------------------------------
#define BATCH 1024
#define NTOK  64
#define CDIM  512
#define NHEAD 8
#define HDIM  64
#define MTOT  (BATCH * NTOK)      // 65536
#define QKVN  (3 * CDIM)          // 1536

// ---------------------------------------------------------------------------
// Device-global scratch (allocation-free)
// ---------------------------------------------------------------------------
__device__ __align__(16) __half  g_qkvh[(size_t)MTOT * QKVN];   // fp16 qkv
__device__ __align__(16) __half  g_xh[(size_t)MTOT * CDIM];
__device__ __align__(16) __half  g_wh[QKVN * CDIM];
__device__ __align__(16) __half  g_ph[CDIM * CDIM];
__device__ __align__(16) __half  g_ao[(size_t)MTOT * CDIM];     // attn out fp16
__device__ __align__(16) float   g_bias[QKVN];
__device__ __align__(16) float   g_cpb[225 * 8];

// ---------------------------------------------------------------------------
// PTX helpers
// ---------------------------------------------------------------------------
__device__ __forceinline__ uint32_t s2u(const void* p) {
    return (uint32_t)__cvta_generic_to_shared(p);
}
__device__ __forceinline__ void cpa16(uint32_t saddr, const void* g) {
    asm volatile("cp.async.cg.shared.global [%0], [%1], 16;" :: "r"(saddr), "l"(g) : "memory");
}
__device__ __forceinline__ void cpa_commit() {
    asm volatile("cp.async.commit_group;" ::: "memory");
}
__device__ __forceinline__ void cpa_wait0() {
    asm volatile("cp.async.wait_group 0;" ::: "memory");
}
#define LDSM4(r, addr) \
    asm volatile("ldmatrix.sync.aligned.m8n8.x4.shared.b16 {%0,%1,%2,%3}, [%4];" \
        : "=r"((r)[0]), "=r"((r)[1]), "=r"((r)[2]), "=r"((r)[3]) : "r"(addr))
#define LDSM4T(r, addr) \
    asm volatile("ldmatrix.sync.aligned.m8n8.x4.trans.shared.b16 {%0,%1,%2,%3}, [%4];" \
        : "=r"((r)[0]), "=r"((r)[1]), "=r"((r)[2]), "=r"((r)[3]) : "r"(addr))
#define MMAH16816(c, a, b0, b1) \
    asm volatile("mma.sync.aligned.m16n8k16.row.col.f32.f16.f16.f32 " \
        "{%0,%1,%2,%3},{%4,%5,%6,%7},{%8,%9},{%0,%1,%2,%3};" \
        : "+f"((c)[0]), "+f"((c)[1]), "+f"((c)[2]), "+f"((c)[3]) \
        : "r"((a)[0]), "r"((a)[1]), "r"((a)[2]), "r"((a)[3]), "r"(b0), "r"(b1))

__device__ __forceinline__ uint32_t h2u(__half2 v) { return *(uint32_t*)&v; }

// ---------------------------------------------------------------------------
// fp32 -> fp16 conversions
// ---------------------------------------------------------------------------
__global__ void conv_h(const float4* __restrict__ in, __half* __restrict__ out, int n4) {
    int stride = gridDim.x * blockDim.x;
    for (int i = blockIdx.x * blockDim.x + threadIdx.x; i < n4; i += stride) {
        float4 v = in[i];
        __half2* op = (__half2*)(out + (size_t)i * 4);
        op[0] = __halves2half2(__float2half(v.x), __float2half(v.y));
        op[1] = __halves2half2(__float2half(v.z), __float2half(v.w));
    }
}

__global__ void conv_h2(const float4* __restrict__ w, __half* __restrict__ wh, int n4w,
                        const float4* __restrict__ p, __half* __restrict__ ph, int n4p) {
    int stride = gridDim.x * blockDim.x;
    int total = n4w + n4p;
    for (int i = blockIdx.x * blockDim.x + threadIdx.x; i < total; i += stride) {
        const float4* src; __half* dst; int idx;
        if (i < n4w) { src = w; dst = wh; idx = i; }
        else         { src = p; dst = ph; idx = i - n4w; }
        float4 v = src[idx];
        __half2* op = (__half2*)(dst + (size_t)idx * 4);
        op[0] = __halves2half2(__float2half(v.x), __float2half(v.y));
        op[1] = __halves2half2(__float2half(v.z), __float2half(v.w));
    }
}

// ---------------------------------------------------------------------------
// CPB MLP + bias build in one launch
// ---------------------------------------------------------------------------
__device__ __forceinline__ float signed_log_coord(int d) {
    float g = (float)d / 7.0f * 8.0f;
    float s = (g > 0.f) ? 1.f : ((g < 0.f) ? -1.f : 0.f);
    return s * log2f(fabsf(g) + 1.0f) / log2f(9.0f);
}
__global__ void cpb_bias_kernel(const float* __restrict__ w1, const float* __restrict__ b1,
                                const float* __restrict__ w2,
                                const float* __restrict__ qb, const float* __restrict__ vb) {
    int t = blockIdx.x;
    if (t >= 225) {
        int i = (t - 225) * 64 + threadIdx.x;
        if (threadIdx.x < 64 && i < QKVN)
            g_bias[i] = (i < 512) ? qb[i] : ((i < 1024) ? 0.f : vb[i - 1024]);
        return;
    }
    float c0 = signed_log_coord(t / 15 - 7);
    float c1 = signed_log_coord(t % 15 - 7);
    __shared__ float red[64][8];
    float p[8];
#pragma unroll
    for (int h = 0; h < 8; h++) p[h] = 0.f;
    for (int j = threadIdx.x; j < 512; j += 64) {
        float hx = fmaf(c0, w1[2 * j], fmaf(c1, w1[2 * j + 1], b1[j]));
        hx = fmaxf(hx, 0.f);
#pragma unroll
        for (int h = 0; h < 8; h++) p[h] += hx * w2[h * 512 + j];
    }
#pragma unroll
    for (int h = 0; h < 8; h++) red[threadIdx.x][h] = p[h];
    __syncthreads();
    if (threadIdx.x < 8) {
        float s = 0.f;
#pragma unroll
        for (int i = 0; i < 64; i++) s += red[i][threadIdx.x];
        g_cpb[t * 8 + threadIdx.x] = 16.f / (1.f + expf(-s));
    }
}

// ---------------------------------------------------------------------------
// B-resident HMMA GEMM: C[M,N] = A[M,512] @ B[N,512]^T + bias[n]
// CTA tile 256x128, 512 threads (16 warps, 8x2), warp tile 32x64.
// B (128x512 fp16) resident in smem for all K; A double-buffered per BK=64.
// 1 CTA/SM.
// ---------------------------------------------------------------------------
#define BSTR 1040                    // B row stride bytes (1024 data + 16 pad)
#define B_BYTES (128 * BSTR)         // 133120
#define ALDT 144                     // A row stride bytes
#define ASTG (256 * ALDT)            // 36864 per A stage
#define GEMM_SMEM (B_BYTES + 2 * ASTG)  // 206848

__device__ __forceinline__ void load_B(uint32_t sB, const __half* __restrict__ B,
                                       int n0, int tid) {
#pragma unroll
    for (int i = 0; i < 16; i++) {
        int id = tid + i * 512;          // 0..8191
        int r = id >> 6, c = id & 63;    // r: n row 0..127, c: 8-half chunk 0..63
        cpa16(sB + (uint32_t)(r * BSTR + c * 16),
              B + (size_t)(n0 + r) * CDIM + c * 8);
    }
    cpa_commit();
}

__device__ __forceinline__ void load_A(uint32_t sA, int kt,
                                       const __half* __restrict__ A,
                                       int m0, int tid) {
    const int k0 = kt * 64;
#pragma unroll
    for (int i = 0; i < 4; i++) {
        int id = tid + i * 512;          // 0..2047
        int r = id >> 3, c = id & 7;     // r: 0..255, c: 0..7
        cpa16(sA + (uint32_t)(r * ALDT + c * 16),
              A + (size_t)(m0 + r) * CDIM + k0 + c * 8);
    }
    cpa_commit();
}

template <bool HALF_OUT>
__global__ void __launch_bounds__(512, 1)
gemm_bres(const __half* __restrict__ A, const __half* __restrict__ B,
          float* __restrict__ Cf, __half* __restrict__ Ch,
          const float* __restrict__ bias, int ldc) {
    extern __shared__ char dsm[];
    const uint32_t sB = s2u(dsm);
    const uint32_t sA = sB + B_BYTES;

    const int tid = threadIdx.x;
    const int wid = tid >> 5;
    const int lane = tid & 31;
    const int wm = wid & 7;           // 8 m-warps: rows wm*32
    const int wn = wid >> 3;          // 2 n-warps: cols wn*64
    const int m0 = blockIdx.y * 256;
    const int n0 = blockIdx.x * 128;

    float acc[16][4];
#pragma unroll
    for (int t = 0; t < 16; t++)
#pragma unroll
        for (int e = 0; e < 4; e++) acc[t][e] = 0.f;

    // prologue: B (all K) + A stage 0
    load_B(sB, B, n0, tid);
    load_A(sA, 0, A, m0, tid);

    const uint32_t a_row = (uint32_t)((wm * 32 + (lane & 15)) * ALDT + (lane >> 4) * 16);
    const uint32_t b_row = (uint32_t)(((lane & 7) + ((lane >> 4) << 3) + wn * 64) * BSTR
                                      + ((lane >> 3) & 1) * 16);

    const int NK = CDIM / 64;  // 8
    for (int kt = 0; kt < NK; kt++) {
        cpa_wait0();
        __syncthreads();
        if (kt + 1 < NK)
            load_A(sA + (uint32_t)((kt + 1) & 1) * ASTG, kt + 1, A, m0, tid);

        const uint32_t stA = sA + (uint32_t)(kt & 1) * ASTG;
        const uint32_t bk = (uint32_t)(kt * 128);   // 64 halves = 128 bytes
#pragma unroll
        for (int ks = 0; ks < 4; ks++) {
            const uint32_t koff = (uint32_t)(ks * 32);
            uint32_t bh[4][4];
#pragma unroll
            for (int ng = 0; ng < 4; ng++) {
                LDSM4(bh[ng], sB + b_row + (uint32_t)(ng * 16 * BSTR) + bk + koff);
            }
#pragma unroll
            for (int i = 0; i < 2; i++) {
                uint32_t ah[4];
                LDSM4(ah, stA + a_row + (uint32_t)(i * 16 * ALDT) + koff);
#pragma unroll
                for (int j = 0; j < 8; j++) {
                    float* c = acc[i * 8 + j];
                    int ng = j >> 1, sb = (j & 1) * 2;
                    MMAH16816(c, ah, bh[ng][sb], bh[ng][sb + 1]);
                }
            }
        }
    }

#pragma unroll
    for (int i = 0; i < 2; i++) {
#pragma unroll
        for (int j = 0; j < 8; j++) {
            const float* c = acc[i * 8 + j];
            int row = m0 + wm * 32 + i * 16 + (lane >> 2);
            int col = n0 + wn * 64 + j * 8 + (lane & 3) * 2;
            float2 b2 = __ldg((const float2*)(bias + col));
            if (HALF_OUT) {
                __half2 v0 = __floats2half2_rn(c[0] + b2.x, c[1] + b2.y);
                __half2 v1 = __floats2half2_rn(c[2] + b2.x, c[3] + b2.y);
                *(__half2*)(Ch + (size_t)row * ldc + col) = v0;
                *(__half2*)(Ch + (size_t)(row + 8) * ldc + col) = v1;
            } else {
                float2 v0 = make_float2(c[0] + b2.x, c[1] + b2.y);
                float2 v1 = make_float2(c[2] + b2.x, c[3] + b2.y);
                *(float2*)(Cf + (size_t)row * ldc + col) = v0;
                *(float2*)(Cf + (size_t)(row + 8) * ldc + col) = v1;
            }
        }
    }
}

// ---------------------------------------------------------------------------
// HMMA fused attention. grid=(1024,8), 128 threads (4 warps, 16 rows each).
// Deferred normalization: S_raw = q@k^T (fp16 MMA), scaled by rinv in fp32.
// ---------------------------------------------------------------------------
#define LDV 72    // halves per smem row (144 B): conflict-free ldmatrix phases
#define ATTN_SMEM (3 * 64 * LDV * 2 + (64 + 64 + 225) * 4)

__global__ void __launch_bounds__(128)
attn_mma(const float* __restrict__ mask, const float* __restrict__ logit_scale) {
    const int b = blockIdx.x;
    const int h = blockIdx.y;
    extern __shared__ char smc[];
    __half* sq = (__half*)smc;
    __half* sk = sq + 64 * LDV;
    __half* sv = sk + 64 * LDV;
    float* rq = (float*)(sv + 64 * LDV);
    float* rk = rq + 64;
    float* scpb = rk + 64;

    const int tid = threadIdx.x;
    const int wid = tid >> 5;
    const int lane = tid & 31;

    const __half* gbase = g_qkvh + (size_t)b * NTOK * QKVN + h * HDIM;
#pragma unroll
    for (int i = 0; i < 4; i++) {
        int idx = tid + i * 128;          // 0..511
        int r = idx >> 3, c = idx & 7;
        const __half* rp = gbase + (size_t)r * QKVN + c * 8;
        uint4 qv = *(const uint4*)(rp);
        uint4 kv = *(const uint4*)(rp + CDIM);
        uint4 vv = *(const uint4*)(rp + 2 * CDIM);
        *(uint4*)(sq + r * LDV + c * 8) = qv;
        *(uint4*)(sk + r * LDV + c * 8) = kv;
        *(uint4*)(sv + r * LDV + c * 8) = vv;
    }
    for (int i = tid; i < 225; i += 128) scpb[i] = g_cpb[i * 8 + h];
    __syncthreads();

    // inverse row norms: threads 0-63 -> q rows, 64-127 -> k rows
    {
        int r = tid & 63;
        const __half* row = (tid < 64 ? sq : sk) + r * LDV;
        float s0 = 0.f, s1 = 0.f;
#pragma unroll
        for (int c = 0; c < 8; c++) {
            uint4 u = *(const uint4*)(row + c * 8);
            const __half2* hp = (const __half2*)&u;
#pragma unroll
            for (int t2 = 0; t2 < 4; t2++) {
                float2 f = __half22float2(hp[t2]);
                s0 = fmaf(f.x, f.x, s0);
                s1 = fmaf(f.y, f.y, s1);
            }
        }
        float inv = 1.f / fmaxf(sqrtf(s0 + s1), 1e-12f);
        (tid < 64 ? rq : rk)[r] = inv;
    }
    __syncthreads();

    const int r0 = wid * 16;
    const uint32_t qbase = s2u(sq) +
        (uint32_t)(((r0 + (lane & 15)) * LDV + ((lane >> 4) & 1) * 8) * 2);
    const uint32_t kbase = s2u(sk) +
        (uint32_t)((((lane & 7) + ((lane >> 4) << 3)) * LDV + ((lane >> 3) & 1) * 8) * 2);

    float sacc[8][4];
#pragma unroll
    for (int f = 0; f < 8; f++)
#pragma unroll
        for (int e = 0; e < 4; e++) sacc[f][e] = 0.f;

#pragma unroll
    for (int kg = 0; kg < 4; kg++) {
        uint32_t aq[4];
        LDSM4(aq, qbase + (uint32_t)(kg * 32));
#pragma unroll
        for (int ng = 0; ng < 4; ng++) {
            uint32_t bk[4];
            LDSM4(bk, kbase + (uint32_t)(ng * 16 * LDV * 2 + kg * 32));
            MMAH16816(sacc[ng * 2],     aq, bk[0], bk[1]);
            MMAH16816(sacc[ng * 2 + 1], aq, bk[2], bk[3]);
        }
    }

    const float sc = expf(fminf(logit_scale[h], 4.605170185988091f));
    const int rlo = r0 + (lane >> 2);
    const int rhi = rlo + 8;
    const float qlo = rq[rlo] * sc;
    const float qhi = rq[rhi] * sc;
    const float* mrow = mask + (size_t)(b & 63) * NTOK * NTOK;
#pragma unroll
    for (int nf = 0; nf < 8; nf++) {
        int c0 = nf * 8 + (lane & 3) * 2;
        float rk0 = rk[c0], rk1 = rk[c0 + 1];
        float2 mlo2 = __ldg((const float2*)(mrow + rlo * 64 + c0));
        float2 mhi2 = __ldg((const float2*)(mrow + rhi * 64 + c0));
        int tlo = ((rlo >> 3) - (c0 >> 3) + 7) * 15 + ((rlo & 7) - (c0 & 7) + 7);
        int thi = tlo + 15;
        sacc[nf][0] = sacc[nf][0] * qlo * rk0 + scpb[tlo] + mlo2.x;
        sacc[nf][1] = sacc[nf][1] * qlo * rk1 + scpb[tlo - 1] + mlo2.y;
        sacc[nf][2] = sacc[nf][2] * qhi * rk0 + scpb[thi] + mhi2.x;
        sacc[nf][3] = sacc[nf][3] * qhi * rk1 + scpb[thi - 1] + mhi2.y;
    }

    float mlo = -1e30f, mhi = -1e30f;
#pragma unroll
    for (int nf = 0; nf < 8; nf++) {
        mlo = fmaxf(mlo, fmaxf(sacc[nf][0], sacc[nf][1]));
        mhi = fmaxf(mhi, fmaxf(sacc[nf][2], sacc[nf][3]));
    }
#pragma unroll
    for (int o = 1; o <= 2; o <<= 1) {
        mlo = fmaxf(mlo, __shfl_xor_sync(0xffffffffu, mlo, o));
        mhi = fmaxf(mhi, __shfl_xor_sync(0xffffffffu, mhi, o));
    }
    float slo = 0.f, shi = 0.f;
#pragma unroll
    for (int nf = 0; nf < 8; nf++) {
        sacc[nf][0] = __expf(sacc[nf][0] - mlo); slo += sacc[nf][0];
        sacc[nf][1] = __expf(sacc[nf][1] - mlo); slo += sacc[nf][1];
        sacc[nf][2] = __expf(sacc[nf][2] - mhi); shi += sacc[nf][2];
        sacc[nf][3] = __expf(sacc[nf][3] - mhi); shi += sacc[nf][3];
    }
#pragma unroll
    for (int o = 1; o <= 2; o <<= 1) {
        slo += __shfl_xor_sync(0xffffffffu, slo, o);
        shi += __shfl_xor_sync(0xffffffffu, shi, o);
    }
    const float ilo = 1.f / slo, ihi = 1.f / shi;

    uint32_t pa[4][4];
#pragma unroll
    for (int g = 0; g < 4; g++) {
        pa[g][0] = h2u(__floats2half2_rn(sacc[2 * g][0] * ilo, sacc[2 * g][1] * ilo));
        pa[g][1] = h2u(__floats2half2_rn(sacc[2 * g][2] * ihi, sacc[2 * g][3] * ihi));
        pa[g][2] = h2u(__floats2half2_rn(sacc[2 * g + 1][0] * ilo, sacc[2 * g + 1][1] * ilo));
        pa[g][3] = h2u(__floats2half2_rn(sacc[2 * g + 1][2] * ihi, sacc[2 * g + 1][3] * ihi));
    }

    float oacc[8][4];
#pragma unroll
    for (int f = 0; f < 8; f++)
#pragma unroll
        for (int e = 0; e < 4; e++) oacc[f][e] = 0.f;

    const uint32_t vbase = s2u(sv) +
        (uint32_t)(((lane & 15) * LDV + ((lane >> 4) & 1) * 8) * 2);
#pragma unroll
    for (int kg = 0; kg < 4; kg++) {
#pragma unroll
        for (int ng = 0; ng < 4; ng++) {
            uint32_t bv[4];
            LDSM4T(bv, vbase + (uint32_t)(kg * 16 * LDV * 2 + ng * 32));
            MMAH16816(oacc[ng * 2],     pa[kg], bv[0], bv[1]);
            MMAH16816(oacc[ng * 2 + 1], pa[kg], bv[2], bv[3]);
        }
    }

#pragma unroll
    for (int nf = 0; nf < 8; nf++) {
        int col = h * HDIM + nf * 8 + (lane & 3) * 2;
        size_t offlo = (size_t)(b * NTOK + rlo) * CDIM + col;
        size_t offhi = (size_t)(b * NTOK + rhi) * CDIM + col;
        *(__half2*)(g_ao + offlo) = __floats2half2_rn(oacc[nf][0], oacc[nf][1]);
        *(__half2*)(g_ao + offhi) = __floats2half2_rn(oacc[nf][2], oacc[nf][3]);
    }
}

// ---------------------------------------------------------------------------
// launch
// ---------------------------------------------------------------------------
extern "C" void kernel_launch(void* const* d_in, const int* in_sizes, int n_in,
                              void* d_out, int out_size) {
    const float* x           = (const float*)d_in[0];
    const float* mask        = (const float*)d_in[1];
    const float* qkv_w       = (const float*)d_in[2];
    const float* q_bias      = (const float*)d_in[3];
    const float* v_bias      = (const float*)d_in[4];
    const float* logit_scale = (const float*)d_in[5];
    const float* cpb_w1      = (const float*)d_in[6];
    const float* cpb_b1      = (const float*)d_in[7];
    const float* cpb_w2      = (const float*)d_in[8];
    const float* proj_w      = (const float*)d_in[9];
    const float* proj_b      = (const float*)d_in[10];
    float* out = (float*)d_out;

    float* bias_p;
    __half *qkvh, *xh, *wh, *ph, *ao;
    cudaGetSymbolAddress((void**)&qkvh, g_qkvh);
    cudaGetSymbolAddress((void**)&bias_p, g_bias);
    cudaGetSymbolAddress((void**)&xh, g_xh);
    cudaGetSymbolAddress((void**)&wh, g_wh);
    cudaGetSymbolAddress((void**)&ph, g_ph);
    cudaGetSymbolAddress((void**)&ao, g_ao);

    cudaFuncSetAttribute((const void*)gemm_bres<true>,
                         cudaFuncAttributeMaxDynamicSharedMemorySize, GEMM_SMEM);
    cudaFuncSetAttribute((const void*)gemm_bres<false>,
                         cudaFuncAttributeMaxDynamicSharedMemorySize, GEMM_SMEM);
    cudaFuncSetAttribute(attn_mma, cudaFuncAttributeMaxDynamicSharedMemorySize, ATTN_SMEM);

    // conversions + tables
    conv_h<<<8192, 256>>>((const float4*)x, xh, MTOT * CDIM / 4);
    conv_h2<<<1024, 256>>>((const float4*)qkv_w, wh, QKVN * CDIM / 4,
                           (const float4*)proj_w, ph, CDIM * CDIM / 4);
    cpb_bias_kernel<<<249, 64>>>(cpb_w1, cpb_b1, cpb_w2, q_bias, v_bias);

    // QKV projection (B-resident) -> fp16 qkv: grid (12, 256)
    {
        dim3 grid(QKVN / 128, MTOT / 256);
        gemm_bres<true><<<grid, 512, GEMM_SMEM>>>(xh, wh, nullptr, qkvh, bias_p, QKVN);
    }

    // fused HMMA attention
    {
        dim3 grid(BATCH, NHEAD);
        attn_mma<<<grid, 128, ATTN_SMEM>>>(mask, logit_scale);
    }

    // output projection (B-resident) -> d_out fp32: grid (4, 256)
    {
        dim3 grid(CDIM / 128, MTOT / 256);
        gemm_bres<false><<<grid, 512, GEMM_SMEM>>>(ao, ph, out, nullptr, proj_b, CDIM);
    }
}

// round 15
// speedup vs baseline: 1.1303x; 1.1303x over previous
#include <cuda_runtime.h>
#include <cuda_fp16.h>
#include <cstdint>

// ---------------------------------------------------------------------------
// Problem constants
// ---------------------------------------------------------------------------
#define BATCH 1024
#define NTOK  64
#define CDIM  512
#define NHEAD 8
#define HDIM  64
#define MTOT  (BATCH * NTOK)      // 65536
#define QKVN  (3 * CDIM)          // 1536

// ---------------------------------------------------------------------------
// Device-global scratch (allocation-free)
// ---------------------------------------------------------------------------
__device__ __align__(16) __half  g_qkvh[(size_t)MTOT * QKVN];   // fp16 qkv
__device__ __align__(16) __half  g_xh[(size_t)MTOT * CDIM];
__device__ __align__(16) __half  g_wh[QKVN * CDIM];
__device__ __align__(16) __half  g_ph[CDIM * CDIM];
__device__ __align__(16) __half  g_ao[(size_t)MTOT * CDIM];     // attn out fp16
__device__ __align__(16) float   g_bias[QKVN];
__device__ __align__(16) float   g_cpb[225 * 8];

// ---------------------------------------------------------------------------
// PTX helpers
// ---------------------------------------------------------------------------
__device__ __forceinline__ uint32_t s2u(const void* p) {
    return (uint32_t)__cvta_generic_to_shared(p);
}
__device__ __forceinline__ void cpa16(uint32_t saddr, const void* g) {
    asm volatile("cp.async.cg.shared.global [%0], [%1], 16;" :: "r"(saddr), "l"(g) : "memory");
}
__device__ __forceinline__ void cpa_commit() {
    asm volatile("cp.async.commit_group;" ::: "memory");
}
__device__ __forceinline__ void cpa_wait0() {
    asm volatile("cp.async.wait_group 0;" ::: "memory");
}
#define LDSM4(r, addr) \
    asm volatile("ldmatrix.sync.aligned.m8n8.x4.shared.b16 {%0,%1,%2,%3}, [%4];" \
        : "=r"((r)[0]), "=r"((r)[1]), "=r"((r)[2]), "=r"((r)[3]) : "r"(addr))
#define LDSM4T(r, addr) \
    asm volatile("ldmatrix.sync.aligned.m8n8.x4.trans.shared.b16 {%0,%1,%2,%3}, [%4];" \
        : "=r"((r)[0]), "=r"((r)[1]), "=r"((r)[2]), "=r"((r)[3]) : "r"(addr))
#define MMAH16816(c, a, b0, b1) \
    asm volatile("mma.sync.aligned.m16n8k16.row.col.f32.f16.f16.f32 " \
        "{%0,%1,%2,%3},{%4,%5,%6,%7},{%8,%9},{%0,%1,%2,%3};" \
        : "+f"((c)[0]), "+f"((c)[1]), "+f"((c)[2]), "+f"((c)[3]) \
        : "r"((a)[0]), "r"((a)[1]), "r"((a)[2]), "r"((a)[3]), "r"(b0), "r"(b1))

__device__ __forceinline__ uint32_t h2u(__half2 v) { return *(uint32_t*)&v; }

// ---------------------------------------------------------------------------
// fp32 -> fp16 conversions
// ---------------------------------------------------------------------------
__global__ void conv_h(const float4* __restrict__ in, __half* __restrict__ out, int n4) {
    int stride = gridDim.x * blockDim.x;
    for (int i = blockIdx.x * blockDim.x + threadIdx.x; i < n4; i += stride) {
        float4 v = in[i];
        __half2* op = (__half2*)(out + (size_t)i * 4);
        op[0] = __halves2half2(__float2half(v.x), __float2half(v.y));
        op[1] = __halves2half2(__float2half(v.z), __float2half(v.w));
    }
}

__global__ void conv_h2(const float4* __restrict__ w, __half* __restrict__ wh, int n4w,
                        const float4* __restrict__ p, __half* __restrict__ ph, int n4p) {
    int stride = gridDim.x * blockDim.x;
    int total = n4w + n4p;
    for (int i = blockIdx.x * blockDim.x + threadIdx.x; i < total; i += stride) {
        const float4* src; __half* dst; int idx;
        if (i < n4w) { src = w; dst = wh; idx = i; }
        else         { src = p; dst = ph; idx = i - n4w; }
        float4 v = src[idx];
        __half2* op = (__half2*)(dst + (size_t)idx * 4);
        op[0] = __halves2half2(__float2half(v.x), __float2half(v.y));
        op[1] = __halves2half2(__float2half(v.z), __float2half(v.w));
    }
}

// ---------------------------------------------------------------------------
// CPB MLP + bias build in one launch
// ---------------------------------------------------------------------------
__device__ __forceinline__ float signed_log_coord(int d) {
    float g = (float)d / 7.0f * 8.0f;
    float s = (g > 0.f) ? 1.f : ((g < 0.f) ? -1.f : 0.f);
    return s * log2f(fabsf(g) + 1.0f) / log2f(9.0f);
}
__global__ void cpb_bias_kernel(const float* __restrict__ w1, const float* __restrict__ b1,
                                const float* __restrict__ w2,
                                const float* __restrict__ qb, const float* __restrict__ vb) {
    int t = blockIdx.x;
    if (t >= 225) {
        int i = (t - 225) * 64 + threadIdx.x;
        if (threadIdx.x < 64 && i < QKVN)
            g_bias[i] = (i < 512) ? qb[i] : ((i < 1024) ? 0.f : vb[i - 1024]);
        return;
    }
    float c0 = signed_log_coord(t / 15 - 7);
    float c1 = signed_log_coord(t % 15 - 7);
    __shared__ float red[64][8];
    float p[8];
#pragma unroll
    for (int h = 0; h < 8; h++) p[h] = 0.f;
    for (int j = threadIdx.x; j < 512; j += 64) {
        float hx = fmaf(c0, w1[2 * j], fmaf(c1, w1[2 * j + 1], b1[j]));
        hx = fmaxf(hx, 0.f);
#pragma unroll
        for (int h = 0; h < 8; h++) p[h] += hx * w2[h * 512 + j];
    }
#pragma unroll
    for (int h = 0; h < 8; h++) red[threadIdx.x][h] = p[h];
    __syncthreads();
    if (threadIdx.x < 8) {
        float s = 0.f;
#pragma unroll
        for (int i = 0; i < 64; i++) s += red[i][threadIdx.x];
        g_cpb[t * 8 + threadIdx.x] = 16.f / (1.f + expf(-s));
    }
}

// ---------------------------------------------------------------------------
// HMMA GEMM (1-pass fp16): C[M,N] = A[M,512] @ B[N,512]^T + bias[n]
// Tile 128x128x64, 8 warps as 4x2 (warp tile 32x64), 2-stage cp.async,
// 2 CTAs/SM.  (R12 configuration — measured best.)
// ---------------------------------------------------------------------------
#define LDT 144                      // 128 B data + 16 pad per row
#define TILE_BYTES (128 * LDT)       // 18432
#define STAGE_SZ (2 * TILE_BYTES)    // A + B: 36864
#define GEMM_SMEM (2 * STAGE_SZ)     // 73728

__device__ __forceinline__ void load_stage(
    uint32_t sbase, int kt,
    const __half* __restrict__ A, const __half* __restrict__ B,
    int m0, int n0, int tid) {
    const int k0 = kt * 64;
#pragma unroll
    for (int i = 0; i < 4; i++) {
        int id = tid + i * 256;
        int r = id >> 3, c = id & 7;
        uint32_t so = (uint32_t)(r * LDT + c * 16);
        size_t ga = (size_t)(m0 + r) * CDIM + k0 + c * 8;
        size_t gb = (size_t)(n0 + r) * CDIM + k0 + c * 8;
        cpa16(sbase + so, A + ga);
        cpa16(sbase + TILE_BYTES + so, B + gb);
    }
    cpa_commit();
}

template <bool HALF_OUT>
__global__ void __launch_bounds__(256, 2)
gemm1h(const __half* __restrict__ A, const __half* __restrict__ B,
       float* __restrict__ Cf, __half* __restrict__ Ch,
       const float* __restrict__ bias, int ldc) {
    extern __shared__ char dsm[];
    const uint32_t smb = s2u(dsm);

    const int tid = threadIdx.x;
    const int wid = tid >> 5;
    const int lane = tid & 31;
    const int wm = wid & 3;           // 4 m-warps: rows wm*32
    const int wn = wid >> 2;          // 2 n-warps: cols wn*64
    const int m0 = blockIdx.y * 128;
    const int n0 = blockIdx.x * 128;

    float acc[16][4];
#pragma unroll
    for (int t = 0; t < 16; t++)
#pragma unroll
        for (int e = 0; e < 4; e++) acc[t][e] = 0.f;

    load_stage(smb, 0, A, B, m0, n0, tid);

    const uint32_t a_row = (uint32_t)((wm * 32 + (lane & 15)) * LDT + (lane >> 4) * 16);
    const uint32_t b_row = (uint32_t)((wn * 64 + (lane & 7) + ((lane >> 4) << 3)) * LDT
                                      + ((lane >> 3) & 1) * 16);

    const int NK = CDIM / 64;  // 8
    for (int kt = 0; kt < NK; kt++) {
        cpa_wait0();
        __syncthreads();
        if (kt + 1 < NK)
            load_stage(smb + (uint32_t)((kt + 1) & 1) * STAGE_SZ, kt + 1, A, B, m0, n0, tid);

        const uint32_t st = smb + (uint32_t)(kt & 1) * STAGE_SZ;
#pragma unroll
        for (int ks = 0; ks < 4; ks++) {
            const uint32_t koff = (uint32_t)(ks * 32);
            uint32_t bh[4][4];
#pragma unroll
            for (int ng = 0; ng < 4; ng++) {
                uint32_t bd = st + b_row + (uint32_t)(ng * 16 * LDT) + koff;
                LDSM4(bh[ng], bd + TILE_BYTES);
            }
#pragma unroll
            for (int i = 0; i < 2; i++) {
                uint32_t ah[4];
                uint32_t ad = st + a_row + (uint32_t)(i * 16 * LDT) + koff;
                LDSM4(ah, ad);
#pragma unroll
                for (int j = 0; j < 8; j++) {
                    float* c = acc[i * 8 + j];
                    int ng = j >> 1, sb = (j & 1) * 2;
                    MMAH16816(c, ah, bh[ng][sb], bh[ng][sb + 1]);
                }
            }
        }
    }

#pragma unroll
    for (int i = 0; i < 2; i++) {
#pragma unroll
        for (int j = 0; j < 8; j++) {
            const float* c = acc[i * 8 + j];
            int row = m0 + wm * 32 + i * 16 + (lane >> 2);
            int col = n0 + wn * 64 + j * 8 + (lane & 3) * 2;
            float2 b2 = __ldg((const float2*)(bias + col));
            if (HALF_OUT) {
                __half2 v0 = __floats2half2_rn(c[0] + b2.x, c[1] + b2.y);
                __half2 v1 = __floats2half2_rn(c[2] + b2.x, c[3] + b2.y);
                *(__half2*)(Ch + (size_t)row * ldc + col) = v0;
                *(__half2*)(Ch + (size_t)(row + 8) * ldc + col) = v1;
            } else {
                float2 v0 = make_float2(c[0] + b2.x, c[1] + b2.y);
                float2 v1 = make_float2(c[2] + b2.x, c[3] + b2.y);
                *(float2*)(Cf + (size_t)row * ldc + col) = v0;
                *(float2*)(Cf + (size_t)(row + 8) * ldc + col) = v1;
            }
        }
    }
}

// ---------------------------------------------------------------------------
// HMMA fused attention. grid=(1024,8), 128 threads (4 warps, 16 rows each).
// Loads via cp.async (12 outstanding 16B copies/thread, no register trip).
// ---------------------------------------------------------------------------
#define LDV 72    // halves per smem row (144 B): conflict-free ldmatrix phases
#define ATTN_SMEM (3 * 64 * LDV * 2 + (64 + 64 + 225) * 4)

__global__ void __launch_bounds__(128)
attn_mma(const float* __restrict__ mask, const float* __restrict__ logit_scale) {
    const int b = blockIdx.x;
    const int h = blockIdx.y;
    extern __shared__ char smc[];
    __half* sq = (__half*)smc;
    __half* sk = sq + 64 * LDV;
    __half* sv = sk + 64 * LDV;
    float* rq = (float*)(sv + 64 * LDV);
    float* rk = rq + 64;
    float* scpb = rk + 64;

    const int tid = threadIdx.x;
    const int wid = tid >> 5;
    const int lane = tid & 31;

    // async-load q,k,v fp16 tiles (gmem -> smem, no register round trip)
    const __half* gbase = g_qkvh + (size_t)b * NTOK * QKVN + h * HDIM;
    const uint32_t sqa = s2u(sq), ska = s2u(sk), sva = s2u(sv);
#pragma unroll
    for (int i = 0; i < 4; i++) {
        int idx = tid + i * 128;          // 0..511
        int r = idx >> 3, c = idx & 7;
        const __half* rp = gbase + (size_t)r * QKVN + c * 8;
        uint32_t so = (uint32_t)((r * LDV + c * 8) * 2);
        cpa16(sqa + so, rp);
        cpa16(ska + so, rp + CDIM);
        cpa16(sva + so, rp + 2 * CDIM);
    }
    cpa_commit();
    // cpb table load overlaps with the async copies
    for (int i = tid; i < 225; i += 128) scpb[i] = g_cpb[i * 8 + h];
    cpa_wait0();
    __syncthreads();

    // inverse row norms: threads 0-63 -> q rows, 64-127 -> k rows
    {
        int r = tid & 63;
        const __half* row = (tid < 64 ? sq : sk) + r * LDV;
        float s0 = 0.f, s1 = 0.f;
#pragma unroll
        for (int c = 0; c < 8; c++) {
            uint4 u = *(const uint4*)(row + c * 8);
            const __half2* hp = (const __half2*)&u;
#pragma unroll
            for (int t2 = 0; t2 < 4; t2++) {
                float2 f = __half22float2(hp[t2]);
                s0 = fmaf(f.x, f.x, s0);
                s1 = fmaf(f.y, f.y, s1);
            }
        }
        float inv = 1.f / fmaxf(sqrtf(s0 + s1), 1e-12f);
        (tid < 64 ? rq : rk)[r] = inv;
    }
    __syncthreads();

    const int r0 = wid * 16;
    const uint32_t qbase = sqa +
        (uint32_t)(((r0 + (lane & 15)) * LDV + ((lane >> 4) & 1) * 8) * 2);
    const uint32_t kbase = ska +
        (uint32_t)((((lane & 7) + ((lane >> 4) << 3)) * LDV + ((lane >> 3) & 1) * 8) * 2);

    // S = q @ k^T  (raw, fp16 MMA, fp32 accum)
    float sacc[8][4];
#pragma unroll
    for (int f = 0; f < 8; f++)
#pragma unroll
        for (int e = 0; e < 4; e++) sacc[f][e] = 0.f;

#pragma unroll
    for (int kg = 0; kg < 4; kg++) {
        uint32_t aq[4];
        LDSM4(aq, qbase + (uint32_t)(kg * 32));
#pragma unroll
        for (int ng = 0; ng < 4; ng++) {
            uint32_t bk[4];
            LDSM4(bk, kbase + (uint32_t)(ng * 16 * LDV * 2 + kg * 32));
            MMAH16816(sacc[ng * 2],     aq, bk[0], bk[1]);
            MMAH16816(sacc[ng * 2 + 1], aq, bk[2], bk[3]);
        }
    }

    // scale by rinv_q * rinv_k * logit_scale, add cpb + mask
    const float sc = expf(fminf(logit_scale[h], 4.605170185988091f));
    const int rlo = r0 + (lane >> 2);
    const int rhi = rlo + 8;
    const float qlo = rq[rlo] * sc;
    const float qhi = rq[rhi] * sc;
    const float* mrow = mask + (size_t)(b & 63) * NTOK * NTOK;
#pragma unroll
    for (int nf = 0; nf < 8; nf++) {
        int c0 = nf * 8 + (lane & 3) * 2;
        float rk0 = rk[c0], rk1 = rk[c0 + 1];
        float2 mlo2 = __ldg((const float2*)(mrow + rlo * 64 + c0));
        float2 mhi2 = __ldg((const float2*)(mrow + rhi * 64 + c0));
        int tlo = ((rlo >> 3) - (c0 >> 3) + 7) * 15 + ((rlo & 7) - (c0 & 7) + 7);
        int thi = tlo + 15;
        sacc[nf][0] = sacc[nf][0] * qlo * rk0 + scpb[tlo] + mlo2.x;
        sacc[nf][1] = sacc[nf][1] * qlo * rk1 + scpb[tlo - 1] + mlo2.y;
        sacc[nf][2] = sacc[nf][2] * qhi * rk0 + scpb[thi] + mhi2.x;
        sacc[nf][3] = sacc[nf][3] * qhi * rk1 + scpb[thi - 1] + mhi2.y;
    }

    // register softmax (rows rlo / rhi, 4-lane groups share a row)
    float mlo = -1e30f, mhi = -1e30f;
#pragma unroll
    for (int nf = 0; nf < 8; nf++) {
        mlo = fmaxf(mlo, fmaxf(sacc[nf][0], sacc[nf][1]));
        mhi = fmaxf(mhi, fmaxf(sacc[nf][2], sacc[nf][3]));
    }
#pragma unroll
    for (int o = 1; o <= 2; o <<= 1) {
        mlo = fmaxf(mlo, __shfl_xor_sync(0xffffffffu, mlo, o));
        mhi = fmaxf(mhi, __shfl_xor_sync(0xffffffffu, mhi, o));
    }
    float slo = 0.f, shi = 0.f;
#pragma unroll
    for (int nf = 0; nf < 8; nf++) {
        sacc[nf][0] = __expf(sacc[nf][0] - mlo); slo += sacc[nf][0];
        sacc[nf][1] = __expf(sacc[nf][1] - mlo); slo += sacc[nf][1];
        sacc[nf][2] = __expf(sacc[nf][2] - mhi); shi += sacc[nf][2];
        sacc[nf][3] = __expf(sacc[nf][3] - mhi); shi += sacc[nf][3];
    }
#pragma unroll
    for (int o = 1; o <= 2; o <<= 1) {
        slo += __shfl_xor_sync(0xffffffffu, slo, o);
        shi += __shfl_xor_sync(0xffffffffu, shi, o);
    }
    const float ilo = 1.f / slo, ihi = 1.f / shi;

    // P c-frags -> fp16 A-frags (pure register repack)
    uint32_t pa[4][4];
#pragma unroll
    for (int g = 0; g < 4; g++) {
        pa[g][0] = h2u(__floats2half2_rn(sacc[2 * g][0] * ilo, sacc[2 * g][1] * ilo));
        pa[g][1] = h2u(__floats2half2_rn(sacc[2 * g][2] * ihi, sacc[2 * g][3] * ihi));
        pa[g][2] = h2u(__floats2half2_rn(sacc[2 * g + 1][0] * ilo, sacc[2 * g + 1][1] * ilo));
        pa[g][3] = h2u(__floats2half2_rn(sacc[2 * g + 1][2] * ihi, sacc[2 * g + 1][3] * ihi));
    }

    // O = P @ V  (V via ldmatrix.trans)
    float oacc[8][4];
#pragma unroll
    for (int f = 0; f < 8; f++)
#pragma unroll
        for (int e = 0; e < 4; e++) oacc[f][e] = 0.f;

    const uint32_t vbase = sva +
        (uint32_t)(((lane & 15) * LDV + ((lane >> 4) & 1) * 8) * 2);
#pragma unroll
    for (int kg = 0; kg < 4; kg++) {
#pragma unroll
        for (int ng = 0; ng < 4; ng++) {
            uint32_t bv[4];
            LDSM4T(bv, vbase + (uint32_t)(kg * 16 * LDV * 2 + ng * 32));
            MMAH16816(oacc[ng * 2],     pa[kg], bv[0], bv[1]);
            MMAH16816(oacc[ng * 2 + 1], pa[kg], bv[2], bv[3]);
        }
    }

    // write O as single fp16 (input to 1-pass proj GEMM)
#pragma unroll
    for (int nf = 0; nf < 8; nf++) {
        int col = h * HDIM + nf * 8 + (lane & 3) * 2;
        size_t offlo = (size_t)(b * NTOK + rlo) * CDIM + col;
        size_t offhi = (size_t)(b * NTOK + rhi) * CDIM + col;
        *(__half2*)(g_ao + offlo) = __floats2half2_rn(oacc[nf][0], oacc[nf][1]);
        *(__half2*)(g_ao + offhi) = __floats2half2_rn(oacc[nf][2], oacc[nf][3]);
    }
}

// ---------------------------------------------------------------------------
// launch
// ---------------------------------------------------------------------------
extern "C" void kernel_launch(void* const* d_in, const int* in_sizes, int n_in,
                              void* d_out, int out_size) {
    const float* x           = (const float*)d_in[0];
    const float* mask        = (const float*)d_in[1];
    const float* qkv_w       = (const float*)d_in[2];
    const float* q_bias      = (const float*)d_in[3];
    const float* v_bias      = (const float*)d_in[4];
    const float* logit_scale = (const float*)d_in[5];
    const float* cpb_w1      = (const float*)d_in[6];
    const float* cpb_b1      = (const float*)d_in[7];
    const float* cpb_w2      = (const float*)d_in[8];
    const float* proj_w      = (const float*)d_in[9];
    const float* proj_b      = (const float*)d_in[10];
    float* out = (float*)d_out;

    float* bias_p;
    __half *qkvh, *xh, *wh, *ph, *ao;
    cudaGetSymbolAddress((void**)&qkvh, g_qkvh);
    cudaGetSymbolAddress((void**)&bias_p, g_bias);
    cudaGetSymbolAddress((void**)&xh, g_xh);
    cudaGetSymbolAddress((void**)&wh, g_wh);
    cudaGetSymbolAddress((void**)&ph, g_ph);
    cudaGetSymbolAddress((void**)&ao, g_ao);

    cudaFuncSetAttribute((const void*)gemm1h<true>,
                         cudaFuncAttributeMaxDynamicSharedMemorySize, GEMM_SMEM);
    cudaFuncSetAttribute((const void*)gemm1h<false>,
                         cudaFuncAttributeMaxDynamicSharedMemorySize, GEMM_SMEM);
    cudaFuncSetAttribute(attn_mma, cudaFuncAttributeMaxDynamicSharedMemorySize, ATTN_SMEM);

    // conversions + tables
    conv_h<<<8192, 256>>>((const float4*)x, xh, MTOT * CDIM / 4);
    conv_h2<<<1024, 256>>>((const float4*)qkv_w, wh, QKVN * CDIM / 4,
                           (const float4*)proj_w, ph, CDIM * CDIM / 4);
    cpb_bias_kernel<<<249, 64>>>(cpb_w1, cpb_b1, cpb_w2, q_bias, v_bias);

    // QKV projection (1-pass) -> fp16 qkv: grid (12, 512)
    {
        dim3 grid(QKVN / 128, MTOT / 128);
        gemm1h<true><<<grid, 256, GEMM_SMEM>>>(xh, wh, nullptr, qkvh, bias_p, QKVN);
    }

    // fused HMMA attention
    {
        dim3 grid(BATCH, NHEAD);
        attn_mma<<<grid, 128, ATTN_SMEM>>>(mask, logit_scale);
    }

    // output projection (1-pass) -> d_out fp32: grid (4, 512)
    {
        dim3 grid(CDIM / 128, MTOT / 128);
        gemm1h<false><<<grid, 256, GEMM_SMEM>>>(ao, ph, out, nullptr, proj_b, CDIM);
    }
}